// round 7
// baseline (speedup 1.0000x reference)
#include <cuda_runtime.h>

#define BDIM 128
#define HDIM 32
#define SDIM 64
#define DDIM 128
#define STARTLEN 32
#define NT 256
#define BSTR (HDIM * SDIM * DDIM)

// SMEM (floats): Ks[2][64][128]=16384, cur[2][128]=256, red[20][128]=2560
// q overlays RED rows 0-1; att (scores) overlays RED rows 2-3; AV partials rows 4-11.
#define KS   0
#define CUR  16384
#define RED  16640
#define ATTB (RED + 2 * DDIM)
#define SMEM_FLOATS 19200            // 76800 B -> 3 CTAs/SM

// Fused weights per head, concatenated: [h][384][128] (Wo@Wq | Wo@Wk | Wo@Wv)
__device__ float g_comb[HDIM * 3 * DDIM * DDIM];   // 6 MB scratch

// ---------------- fuse kernel: C = Wo @ Wm, register-tiled ----------------
__global__ void __launch_bounds__(256)
fuse_weights_kernel(const float* __restrict__ wq, const float* __restrict__ wk,
                    const float* __restrict__ wv, const float* __restrict__ wo)
{
    __shared__ float Ws[DDIM * DDIM];       // Wm  (64 KB)
    __shared__ float Wop[64 * DDIM];        // Wo row panel (32 KB)
    const int h    = blockIdx.x / 6;
    const int rem  = blockIdx.x % 6;
    const int m    = rem >> 1;
    const int d0   = (rem & 1) << 6;
    const int t    = threadIdx.x;

    const float* Wm = ((m == 0) ? wq : ((m == 1) ? wk : wv)) + (size_t)h * DDIM * DDIM;
    const float* Wo = wo + (size_t)h * DDIM * DDIM;

    for (int i = t; i < DDIM * DDIM / 4; i += 256)
        ((float4*)Ws)[i] = ((const float4*)Wm)[i];
    for (int i = t; i < 64 * DDIM / 4; i += 256)
        ((float4*)Wop)[i] = ((const float4*)(Wo + d0 * DDIM))[i];
    __syncthreads();

    const int c = t & 15;
    const int r = t >> 4;
    float acc[4][8];
    #pragma unroll
    for (int i = 0; i < 4; ++i)
        #pragma unroll
        for (int j = 0; j < 8; ++j) acc[i][j] = 0.f;

    #pragma unroll 4
    for (int e = 0; e < DDIM; ++e) {
        float4 wm0 = *(const float4*)&Ws[e * DDIM + c * 8];
        float4 wm1 = *(const float4*)&Ws[e * DDIM + c * 8 + 4];
        #pragma unroll
        for (int i = 0; i < 4; ++i) {
            float wo_v = Wop[(r * 4 + i) * DDIM + e];
            acc[i][0] += wo_v * wm0.x; acc[i][1] += wo_v * wm0.y;
            acc[i][2] += wo_v * wm0.z; acc[i][3] += wo_v * wm0.w;
            acc[i][4] += wo_v * wm1.x; acc[i][5] += wo_v * wm1.y;
            acc[i][6] += wo_v * wm1.z; acc[i][7] += wo_v * wm1.w;
        }
    }

    float* dst = g_comb + ((size_t)h * 384 + m * DDIM + d0) * DDIM;
    #pragma unroll
    for (int i = 0; i < 4; ++i) {
        *(float4*)&dst[(r * 4 + i) * DDIM + c * 8]     = make_float4(acc[i][0], acc[i][1], acc[i][2], acc[i][3]);
        *(float4*)&dst[(r * 4 + i) * DDIM + c * 8 + 4] = make_float4(acc[i][4], acc[i][5], acc[i][6], acc[i][7]);
    }
}

// ---------------- decode kernel ----------------
__global__ void __launch_bounds__(NT, 3)
attn_decode_kernel(const float* __restrict__ x_in,
                   const float* __restrict__ k_in,
                   const float* __restrict__ v_in,
                   const float* __restrict__ wq,
                   const float* __restrict__ wk,
                   const float* __restrict__ wv,
                   const float* __restrict__ wo,
                   float* k_out, float* v_out, float* __restrict__ x_out)
{
    extern __shared__ float sm[];

    const int t = threadIdx.x;
    const int w = t >> 5;
    const int l = t & 31;
    const int h  = blockIdx.x >> 6;
    const int b0 = (blockIdx.x & 63) << 1;

    float* kg = k_out + (size_t)(b0 * HDIM + h) * (SDIM * DDIM);
    float* vg = v_out + (size_t)(b0 * HDIM + h) * (SDIM * DDIM);

    // ---- prologue: K -> smem + k_out, V -> v_out, x -> cur ----
    for (int b = 0; b < 2; ++b) {
        const float4* kin = (const float4*)(k_in + (size_t)((b0 + b) * HDIM + h) * (SDIM * DDIM));
        const float4* vin = (const float4*)(v_in + (size_t)((b0 + b) * HDIM + h) * (SDIM * DDIM));
        float4* kd = (float4*)(kg + (size_t)b * BSTR);
        float4* vd = (float4*)(vg + (size_t)b * BSTR);
        for (int i = t; i < SDIM * DDIM / 4; i += NT) {
            float4 kv = kin[i];
            *(float4*)&sm[KS + b * 8192 + 4 * i] = kv;
            kd[i] = kv;
            vd[i] = vin[i];
        }
        const float* xin = x_in + (size_t)((b0 + b) * HDIM + h) * DDIM;
        for (int d = t; d < DDIM; d += NT) sm[CUR + b * DDIM + d] = xin[d];
    }
    __syncthreads();

    // P1 flat split: 384 rows (q|k|v), warp w -> rows [48w, 48w+48)
    const int r0  = w * 48;
    const int mA  = r0 >> 7;
    const int dA  = r0 & 127;
    const int nA  = min(48, 128 - dA);
    const int nB  = 48 - nA;
    const int extra = (w > 2) + (w > 5);
    const int slotA = w + extra;
    const int slotB = slotA + 1;

    const float* origM[3] = { wq + (size_t)h * DDIM * DDIM,
                              wk + (size_t)h * DDIM * DDIM,
                              wv + (size_t)h * DDIM * DDIM };
    const float* Ch = g_comb + (size_t)h * 384 * DDIM;

    const float4* origA4  = (const float4*)(origM[mA] + (size_t)dA * DDIM);
    const float4* fusedA4 = (const float4*)(Ch + (size_t)r0 * DDIM);
    const float4* origB4  = (nB > 0) ? (const float4*)origM[mA + 1] : nullptr;
    const float4* fusedB4 = (const float4*)(Ch + (size_t)(r0 + nA) * DDIM);

    const int p2b = w >> 2, p2s0 = (w & 3) << 4;     // P2: (batch, s-quarter)
    const int p4b = w >> 2, p4q = w & 3;             // P4: (batch, s-quarter)

    for (int gen = STARTLEN; gen < SDIM; ++gen) {
        const bool first = (gen == STARTLEN);

        // ===== P1: balanced projections, deep-MLP unroll =====
        {
            const float4* Wp = first ? origA4 : fusedA4;
            float4 a0 = {0,0,0,0}, a1 = {0,0,0,0};
            #pragma unroll 12
            for (int i = 0; i < nA; ++i) {
                float4 wv4 = Wp[i * 32 + l];
                float x0 = sm[CUR + dA + i];
                float x1 = sm[CUR + DDIM + dA + i];
                a0.x += x0 * wv4.x; a0.y += x0 * wv4.y; a0.z += x0 * wv4.z; a0.w += x0 * wv4.w;
                a1.x += x1 * wv4.x; a1.y += x1 * wv4.y; a1.z += x1 * wv4.z; a1.w += x1 * wv4.w;
            }
            *(float4*)&sm[RED + (slotA * 2 + 0) * DDIM + (l << 2)] = a0;
            *(float4*)&sm[RED + (slotA * 2 + 1) * DDIM + (l << 2)] = a1;
            if (nB > 0) {
                const float4* Wp2 = first ? origB4 : fusedB4;
                float4 c0 = {0,0,0,0}, c1 = {0,0,0,0};
                #pragma unroll 8
                for (int i = 0; i < nB; ++i) {
                    float4 wv4 = Wp2[i * 32 + l];
                    float x0 = sm[CUR + i];
                    float x1 = sm[CUR + DDIM + i];
                    c0.x += x0 * wv4.x; c0.y += x0 * wv4.y; c0.z += x0 * wv4.z; c0.w += x0 * wv4.w;
                    c1.x += x1 * wv4.x; c1.y += x1 * wv4.y; c1.z += x1 * wv4.z; c1.w += x1 * wv4.w;
                }
                *(float4*)&sm[RED + (slotB * 2 + 0) * DDIM + (l << 2)] = c0;
                *(float4*)&sm[RED + (slotB * 2 + 1) * DDIM + (l << 2)] = c1;
            }
        }
        __syncthreads();

        // ===== reduce: q -> RED rows 0-1 (scaled); k -> Ks+kg; v -> vg =====
        {
            const int b = t >> 7, e = t & 127;
            float qv = sm[RED + (0 + b) * DDIM + e] + sm[RED + (2 + b) * DDIM + e]
                     + sm[RED + (4 + b) * DDIM + e];
            float kv = sm[RED + (6 + b) * DDIM + e] + sm[RED + (8 + b) * DDIM + e]
                     + sm[RED + (10 + b) * DDIM + e] + sm[RED + (12 + b) * DDIM + e];
            float vv = sm[RED + (14 + b) * DDIM + e] + sm[RED + (16 + b) * DDIM + e]
                     + sm[RED + (18 + b) * DDIM + e];
            sm[RED + b * DDIM + e] = qv * 0.125f;
            sm[KS + (b * SDIM + gen) * DDIM + e] = kv;
            kg[(size_t)b * BSTR + gen * DDIM + e] = kv;
            vg[(size_t)b * BSTR + gen * DDIM + e] = vv;
        }
        __syncthreads();

        // ===== P2: QK scores -> raw att (RED rows 2-3) =====
        {
            float4 q4 = *(const float4*)&sm[RED + p2b * DDIM + (l << 2)];
            #pragma unroll 8
            for (int r = 0; r < 16; ++r) {
                int s = p2s0 + r;
                float4 k4 = *(const float4*)&sm[KS + (p2b * SDIM + s) * DDIM + (l << 2)];
                float p = k4.x * q4.x + k4.y * q4.y + k4.z * q4.z + k4.w * q4.w;
                #pragma unroll
                for (int o = 16; o > 0; o >>= 1) p += __shfl_xor_sync(0xFFFFFFFFu, p, o);
                if (l == 0) sm[ATTB + p2b * SDIM + s] = p;
            }
        }
        __syncthreads();

        // ===== P4: register softmax (redundant per warp) + AV partials (float4 V) =====
        {
            float s0 = sm[ATTB + p4b * SDIM + l];
            float s1 = sm[ATTB + p4b * SDIM + 32 + l];
            float mx = fmaxf(s0, s1);
            #pragma unroll
            for (int o = 16; o > 0; o >>= 1) mx = fmaxf(mx, __shfl_xor_sync(0xFFFFFFFFu, mx, o));
            float e0 = __expf(s0 - mx);
            float e1 = __expf(s1 - mx);
            float su = e0 + e1;
            #pragma unroll
            for (int o = 16; o > 0; o >>= 1) su += __shfl_xor_sync(0xFFFFFFFFu, su, o);
            float inv = 1.0f / su;
            float p0 = e0 * inv, p1 = e1 * inv;

            float psrc = (p4q < 2) ? p0 : p1;        // warp-uniform select
            const int lbase = (p4q & 1) << 4;
            const float4* vb4 = (const float4*)(vg + (size_t)p4b * BSTR) + (p4q << 9) + l;
            float4 acc = {0,0,0,0};
            #pragma unroll 16
            for (int i = 0; i < 16; ++i) {
                float a = __shfl_sync(0xFFFFFFFFu, psrc, lbase + i);
                float4 v4 = vb4[i * 32];
                acc.x += a * v4.x; acc.y += a * v4.y; acc.z += a * v4.z; acc.w += a * v4.w;
            }
            *(float4*)&sm[RED + (4 + w) * DDIM + (l << 2)] = acc;   // rows 4-11
        }
        __syncthreads();

        // ===== mini-reduce: AV partials -> cur =====
        {
            const int b = t >> 7, d = t & 127;
            float v = sm[RED + (4 + 4 * b + 0) * DDIM + d] + sm[RED + (4 + 4 * b + 1) * DDIM + d]
                    + sm[RED + (4 + 4 * b + 2) * DDIM + d] + sm[RED + (4 + 4 * b + 3) * DDIM + d];
            sm[CUR + b * DDIM + d] = v;
        }
        __syncthreads();
    }

    // ---- epilogue: x_out = cur @ Wo ----
    const float4* Wo4 = (const float4*)(wo + (size_t)h * DDIM * DDIM);
    {
        float4 a0 = {0,0,0,0}, a1 = {0,0,0,0};
        const int d0 = w << 4;
        #pragma unroll 8
        for (int dd = 0; dd < 16; ++dd) {
            int d = d0 + dd;
            float4 wv4 = Wo4[d * 32 + l];
            float x0 = sm[CUR + d];
            float x1 = sm[CUR + DDIM + d];
            a0.x += x0 * wv4.x; a0.y += x0 * wv4.y; a0.z += x0 * wv4.z; a0.w += x0 * wv4.w;
            a1.x += x1 * wv4.x; a1.y += x1 * wv4.y; a1.z += x1 * wv4.z; a1.w += x1 * wv4.w;
        }
        *(float4*)&sm[RED + ((w << 1) + 0) * DDIM + (l << 2)] = a0;
        *(float4*)&sm[RED + ((w << 1) + 1) * DDIM + (l << 2)] = a1;
    }
    __syncthreads();
    {
        const int b = t >> 7, e = t & 127;
        float v = 0.f;
        #pragma unroll
        for (int ww = 0; ww < 8; ++ww)
            v += sm[RED + ((ww << 1) + b) * DDIM + e];
        x_out[(size_t)((b0 + b) * HDIM + h) * DDIM + e] = v;
    }
}

extern "C" void kernel_launch(void* const* d_in, const int* in_sizes, int n_in,
                              void* d_out, int out_size)
{
    const float* x  = (const float*)d_in[0];
    const float* k  = (const float*)d_in[1];
    const float* v  = (const float*)d_in[2];
    const float* wq = (const float*)d_in[3];
    const float* wk = (const float*)d_in[4];
    const float* wv = (const float*)d_in[5];
    const float* wo = (const float*)d_in[6];

    float* out   = (float*)d_out;
    float* k_out = out;
    float* v_out = out + (size_t)BDIM * HDIM * SDIM * DDIM;
    float* x_out = out + (size_t)2 * BDIM * HDIM * SDIM * DDIM;

    fuse_weights_kernel<<<HDIM * 6, 256>>>(wq, wk, wv, wo);

    size_t smem = SMEM_FLOATS * sizeof(float);
    cudaFuncSetAttribute(attn_decode_kernel,
                         cudaFuncAttributeMaxDynamicSharedMemorySize, (int)smem);
    attn_decode_kernel<<<BDIM * HDIM / 2, NT, smem>>>(
        x, k, v, wq, wk, wv, wo, k_out, v_out, x_out);
}

// round 8
// speedup vs baseline: 1.0380x; 1.0380x over previous
#include <cuda_runtime.h>

#define BDIM 128
#define HDIM 32
#define SDIM 64
#define DDIM 128
#define STARTLEN 32
#define NT 256
#define BSTR (HDIM * SDIM * DDIM)

// SMEM (floats): cur[2][128]=256, red[20][128]=2560 (q overlays rows 0-1, att rows 2-3)
#define CUR  0
#define RED  256
#define ATTB (RED + 2 * DDIM)
#define SMEM_FLOATS 2816              // 11264 B -> smem no longer the occupancy limit

// Fused weights per head: [h][384][128]  (Wo@Wq | Wo@Wk | Wo@Wv)
__device__ float g_comb[HDIM * 3 * DDIM * DDIM];

// ---------------- fuse kernel: C = Wo @ Wm, 384 CTAs, 32-row panels ----------------
__global__ void __launch_bounds__(256)
fuse_weights_kernel(const float* __restrict__ wq, const float* __restrict__ wk,
                    const float* __restrict__ wv, const float* __restrict__ wo)
{
    __shared__ float Ws[DDIM * DDIM];       // Wm (64 KB)
    __shared__ float Wop[32 * DDIM];        // Wo 32-row panel (16 KB)
    const int h    = blockIdx.x / 12;
    const int rem  = blockIdx.x % 12;
    const int m    = rem >> 2;
    const int d0   = (rem & 3) << 5;        // 32-row panel
    const int t    = threadIdx.x;

    const float* Wm = ((m == 0) ? wq : ((m == 1) ? wk : wv)) + (size_t)h * DDIM * DDIM;
    const float* Wo = wo + (size_t)h * DDIM * DDIM;

    for (int i = t; i < DDIM * DDIM / 4; i += 256)
        ((float4*)Ws)[i] = ((const float4*)Wm)[i];
    for (int i = t; i < 32 * DDIM / 4; i += 256)
        ((float4*)Wop)[i] = ((const float4*)(Wo + d0 * DDIM))[i];
    __syncthreads();

    const int c = t & 15;                   // 8 cols each
    const int r = t >> 4;                   // 16 groups x 2 rows
    float acc[2][8];
    #pragma unroll
    for (int i = 0; i < 2; ++i)
        #pragma unroll
        for (int j = 0; j < 8; ++j) acc[i][j] = 0.f;

    #pragma unroll 4
    for (int e = 0; e < DDIM; ++e) {
        float4 wm0 = *(const float4*)&Ws[e * DDIM + c * 8];
        float4 wm1 = *(const float4*)&Ws[e * DDIM + c * 8 + 4];
        #pragma unroll
        for (int i = 0; i < 2; ++i) {
            float wo_v = Wop[(r * 2 + i) * DDIM + e];
            acc[i][0] += wo_v * wm0.x; acc[i][1] += wo_v * wm0.y;
            acc[i][2] += wo_v * wm0.z; acc[i][3] += wo_v * wm0.w;
            acc[i][4] += wo_v * wm1.x; acc[i][5] += wo_v * wm1.y;
            acc[i][6] += wo_v * wm1.z; acc[i][7] += wo_v * wm1.w;
        }
    }

    float* dst = g_comb + ((size_t)h * 384 + m * DDIM + d0) * DDIM;
    #pragma unroll
    for (int i = 0; i < 2; ++i) {
        *(float4*)&dst[(r * 2 + i) * DDIM + c * 8]     = make_float4(acc[i][0], acc[i][1], acc[i][2], acc[i][3]);
        *(float4*)&dst[(r * 2 + i) * DDIM + c * 8 + 4] = make_float4(acc[i][4], acc[i][5], acc[i][6], acc[i][7]);
    }
}

// ---------------- decode kernel ----------------
__global__ void __launch_bounds__(NT, 4)
attn_decode_kernel(const float* __restrict__ x_in,
                   const float* __restrict__ k_in,
                   const float* __restrict__ v_in,
                   const float* __restrict__ wq,
                   const float* __restrict__ wk,
                   const float* __restrict__ wv,
                   const float* __restrict__ wo,
                   float* k_out, float* v_out, float* __restrict__ x_out)
{
    __shared__ float sm[SMEM_FLOATS];

    const int t = threadIdx.x;
    const int w = t >> 5;
    const int l = t & 31;
    const int h  = blockIdx.x >> 6;
    const int b0 = (blockIdx.x & 63) << 1;

    float* kg = k_out + (size_t)(b0 * HDIM + h) * (SDIM * DDIM);
    float* vg = v_out + (size_t)(b0 * HDIM + h) * (SDIM * DDIM);

    // ---- prologue: k_in -> k_out, v_in -> v_out (write-through caches), x -> cur ----
    for (int b = 0; b < 2; ++b) {
        const float4* kin = (const float4*)(k_in + (size_t)((b0 + b) * HDIM + h) * (SDIM * DDIM));
        const float4* vin = (const float4*)(v_in + (size_t)((b0 + b) * HDIM + h) * (SDIM * DDIM));
        float4* kd = (float4*)(kg + (size_t)b * BSTR);
        float4* vd = (float4*)(vg + (size_t)b * BSTR);
        for (int i = t; i < SDIM * DDIM / 4; i += NT) {
            kd[i] = kin[i];
            vd[i] = vin[i];
        }
        const float* xin = x_in + (size_t)((b0 + b) * HDIM + h) * DDIM;
        for (int d = t; d < DDIM; d += NT) sm[CUR + b * DDIM + d] = xin[d];
    }
    __syncthreads();

    // P1 flat split: 384 rows (q|k|v), warp w -> rows [48w, 48w+48)
    const int r0  = w * 48;
    const int mA  = r0 >> 7;
    const int dA  = r0 & 127;
    const int nA  = min(48, 128 - dA);
    const int nB  = 48 - nA;
    const int extra = (w > 2) + (w > 5);
    const int slotA = w + extra;
    const int slotB = slotA + 1;

    const float* origM[3] = { wq + (size_t)h * DDIM * DDIM,
                              wk + (size_t)h * DDIM * DDIM,
                              wv + (size_t)h * DDIM * DDIM };
    const float* Ch = g_comb + (size_t)h * 384 * DDIM;

    const float4* origA4  = (const float4*)(origM[mA] + (size_t)dA * DDIM);
    const float4* fusedA4 = (const float4*)(Ch + (size_t)r0 * DDIM);
    const float4* origB4  = (nB > 0) ? (const float4*)origM[mA + 1] : nullptr;
    const float4* fusedB4 = (const float4*)(Ch + (size_t)(r0 + nA) * DDIM);

    const int p2b = w >> 2, p2s0 = (w & 3) << 4;     // P2: (batch, s-quarter)
    const int p4b = t >> 7, p4d = t & 127;           // P4: (batch, d)

    for (int gen = STARTLEN; gen < SDIM; ++gen) {
        const bool first = (gen == STARTLEN);

        // ===== P1: balanced projections (48 rows/warp, 2 batches) =====
        {
            const float4* Wp = first ? origA4 : fusedA4;
            float4 a0 = {0,0,0,0}, a1 = {0,0,0,0};
            #pragma unroll 8
            for (int i = 0; i < nA; ++i) {
                float4 wv4 = Wp[i * 32 + l];
                float x0 = sm[CUR + dA + i];
                float x1 = sm[CUR + DDIM + dA + i];
                a0.x += x0 * wv4.x; a0.y += x0 * wv4.y; a0.z += x0 * wv4.z; a0.w += x0 * wv4.w;
                a1.x += x1 * wv4.x; a1.y += x1 * wv4.y; a1.z += x1 * wv4.z; a1.w += x1 * wv4.w;
            }
            *(float4*)&sm[RED + (slotA * 2 + 0) * DDIM + (l << 2)] = a0;
            *(float4*)&sm[RED + (slotA * 2 + 1) * DDIM + (l << 2)] = a1;
            if (nB > 0) {
                const float4* Wp2 = first ? origB4 : fusedB4;
                float4 c0 = {0,0,0,0}, c1 = {0,0,0,0};
                #pragma unroll 8
                for (int i = 0; i < nB; ++i) {
                    float4 wv4 = Wp2[i * 32 + l];
                    float x0 = sm[CUR + i];
                    float x1 = sm[CUR + DDIM + i];
                    c0.x += x0 * wv4.x; c0.y += x0 * wv4.y; c0.z += x0 * wv4.z; c0.w += x0 * wv4.w;
                    c1.x += x1 * wv4.x; c1.y += x1 * wv4.y; c1.z += x1 * wv4.z; c1.w += x1 * wv4.w;
                }
                *(float4*)&sm[RED + (slotB * 2 + 0) * DDIM + (l << 2)] = c0;
                *(float4*)&sm[RED + (slotB * 2 + 1) * DDIM + (l << 2)] = c1;
            }
        }
        __syncthreads();

        // ===== reduce: q -> RED rows 0-1 (scaled); k -> kg; v -> vg =====
        {
            const int b = t >> 7, e = t & 127;
            float qv = sm[RED + (0 + b) * DDIM + e] + sm[RED + (2 + b) * DDIM + e]
                     + sm[RED + (4 + b) * DDIM + e];
            float kv = sm[RED + (6 + b) * DDIM + e] + sm[RED + (8 + b) * DDIM + e]
                     + sm[RED + (10 + b) * DDIM + e] + sm[RED + (12 + b) * DDIM + e];
            float vv = sm[RED + (14 + b) * DDIM + e] + sm[RED + (16 + b) * DDIM + e]
                     + sm[RED + (18 + b) * DDIM + e];
            sm[RED + b * DDIM + e] = qv * 0.125f;
            kg[(size_t)b * BSTR + gen * DDIM + e] = kv;
            vg[(size_t)b * BSTR + gen * DDIM + e] = vv;
        }
        __syncthreads();

        // ===== P2: QK scores from global K (L2), -> raw att (RED rows 2-3) =====
        {
            float4 q4 = *(const float4*)&sm[RED + p2b * DDIM + (l << 2)];
            const float4* kb4 = (const float4*)(kg + (size_t)p2b * BSTR) + l;
            #pragma unroll 8
            for (int r = 0; r < 16; ++r) {
                int s = p2s0 + r;
                float4 k4 = kb4[s * 32];
                float p = k4.x * q4.x + k4.y * q4.y + k4.z * q4.z + k4.w * q4.w;
                #pragma unroll
                for (int o = 16; o > 0; o >>= 1) p += __shfl_xor_sync(0xFFFFFFFFu, p, o);
                if (l == 0) sm[ATTB + p2b * SDIM + s] = p;
            }
        }
        __syncthreads();

        // ===== P4: per-warp register softmax + AV -> cur =====
        {
            float s0 = sm[ATTB + p4b * SDIM + l];
            float s1 = sm[ATTB + p4b * SDIM + 32 + l];
            float mx = fmaxf(s0, s1);
            #pragma unroll
            for (int o = 16; o > 0; o >>= 1) mx = fmaxf(mx, __shfl_xor_sync(0xFFFFFFFFu, mx, o));
            float e0 = __expf(s0 - mx);
            float e1 = __expf(s1 - mx);
            float su = e0 + e1;
            #pragma unroll
            for (int o = 16; o > 0; o >>= 1) su += __shfl_xor_sync(0xFFFFFFFFu, su, o);
            float inv = 1.0f / su;
            float p0 = e0 * inv, p1 = e1 * inv;

            const float* vb = vg + (size_t)p4b * BSTR + p4d;
            float acc = 0.f;
            #pragma unroll 8
            for (int s = 0; s < 32; ++s) {
                float a = __shfl_sync(0xFFFFFFFFu, p0, s);
                acc += a * vb[s * DDIM];
            }
            #pragma unroll 8
            for (int s = 0; s < 32; ++s) {
                float a = __shfl_sync(0xFFFFFFFFu, p1, s);
                acc += a * vb[(32 + s) * DDIM];
            }
            sm[CUR + p4b * DDIM + p4d] = acc;
        }
        __syncthreads();
    }

    // ---- epilogue: x_out = cur @ Wo ----
    const float4* Wo4 = (const float4*)(wo + (size_t)h * DDIM * DDIM);
    {
        float4 a0 = {0,0,0,0}, a1 = {0,0,0,0};
        const int d0 = w << 4;
        #pragma unroll 8
        for (int dd = 0; dd < 16; ++dd) {
            int d = d0 + dd;
            float4 wv4 = Wo4[d * 32 + l];
            float x0 = sm[CUR + d];
            float x1 = sm[CUR + DDIM + d];
            a0.x += x0 * wv4.x; a0.y += x0 * wv4.y; a0.z += x0 * wv4.z; a0.w += x0 * wv4.w;
            a1.x += x1 * wv4.x; a1.y += x1 * wv4.y; a1.z += x1 * wv4.z; a1.w += x1 * wv4.w;
        }
        *(float4*)&sm[RED + ((w << 1) + 0) * DDIM + (l << 2)] = a0;
        *(float4*)&sm[RED + ((w << 1) + 1) * DDIM + (l << 2)] = a1;
    }
    __syncthreads();
    {
        const int b = t >> 7, e = t & 127;
        float v = 0.f;
        #pragma unroll
        for (int ww = 0; ww < 8; ++ww)
            v += sm[RED + ((ww << 1) + b) * DDIM + e];
        x_out[(size_t)((b0 + b) * HDIM + h) * DDIM + e] = v;
    }
}

extern "C" void kernel_launch(void* const* d_in, const int* in_sizes, int n_in,
                              void* d_out, int out_size)
{
    const float* x  = (const float*)d_in[0];
    const float* k  = (const float*)d_in[1];
    const float* v  = (const float*)d_in[2];
    const float* wq = (const float*)d_in[3];
    const float* wk = (const float*)d_in[4];
    const float* wv = (const float*)d_in[5];
    const float* wo = (const float*)d_in[6];

    float* out   = (float*)d_out;
    float* k_out = out;
    float* v_out = out + (size_t)BDIM * HDIM * SDIM * DDIM;
    float* x_out = out + (size_t)2 * BDIM * HDIM * SDIM * DDIM;

    fuse_weights_kernel<<<HDIM * 12, 256>>>(wq, wk, wv, wo);

    attn_decode_kernel<<<BDIM * HDIM / 2, NT>>>(
        x, k, v, wq, wk, wv, wo, k_out, v_out, x_out);
}

// round 9
// speedup vs baseline: 1.1006x; 1.0603x over previous
#include <cuda_runtime.h>

#define BDIM 128
#define HDIM 32
#define SDIM 64
#define DDIM 128
#define STARTLEN 32
#define NT 256
#define BSTR (HDIM * SDIM * DDIM)

// SMEM (floats): Vs[2][64][128]=16384, cur[2][128]=256, red[20][128]=2560
// q overlays RED rows 0-1; att (scores) overlays RED rows 2-3.
#define VS   0
#define CUR  16384
#define RED  16640
#define ATTB (RED + 2 * DDIM)
#define SMEM_FLOATS 19200            // 76800 B -> 3 CTAs/SM

// Fused weights per head: [h][384][128]  (Wo@Wq | Wo@Wk | Wo@Wv)
__device__ float g_comb[HDIM * 3 * DDIM * DDIM];

// ---------------- fuse kernel: C = Wo @ Wm, 384 CTAs, 32-row panels ----------------
__global__ void __launch_bounds__(256)
fuse_weights_kernel(const float* __restrict__ wq, const float* __restrict__ wk,
                    const float* __restrict__ wv, const float* __restrict__ wo)
{
    __shared__ float Ws[DDIM * DDIM];       // Wm (64 KB)
    __shared__ float Wop[32 * DDIM];        // Wo 32-row panel (16 KB)
    const int h    = blockIdx.x / 12;
    const int rem  = blockIdx.x % 12;
    const int m    = rem >> 2;
    const int d0   = (rem & 3) << 5;
    const int t    = threadIdx.x;

    const float* Wm = ((m == 0) ? wq : ((m == 1) ? wk : wv)) + (size_t)h * DDIM * DDIM;
    const float* Wo = wo + (size_t)h * DDIM * DDIM;

    for (int i = t; i < DDIM * DDIM / 4; i += 256)
        ((float4*)Ws)[i] = ((const float4*)Wm)[i];
    for (int i = t; i < 32 * DDIM / 4; i += 256)
        ((float4*)Wop)[i] = ((const float4*)(Wo + d0 * DDIM))[i];
    __syncthreads();

    const int c = t & 15;
    const int r = t >> 4;
    float acc[2][8];
    #pragma unroll
    for (int i = 0; i < 2; ++i)
        #pragma unroll
        for (int j = 0; j < 8; ++j) acc[i][j] = 0.f;

    #pragma unroll 4
    for (int e = 0; e < DDIM; ++e) {
        float4 wm0 = *(const float4*)&Ws[e * DDIM + c * 8];
        float4 wm1 = *(const float4*)&Ws[e * DDIM + c * 8 + 4];
        #pragma unroll
        for (int i = 0; i < 2; ++i) {
            float wo_v = Wop[(r * 2 + i) * DDIM + e];
            acc[i][0] += wo_v * wm0.x; acc[i][1] += wo_v * wm0.y;
            acc[i][2] += wo_v * wm0.z; acc[i][3] += wo_v * wm0.w;
            acc[i][4] += wo_v * wm1.x; acc[i][5] += wo_v * wm1.y;
            acc[i][6] += wo_v * wm1.z; acc[i][7] += wo_v * wm1.w;
        }
    }

    float* dst = g_comb + ((size_t)h * 384 + m * DDIM + d0) * DDIM;
    #pragma unroll
    for (int i = 0; i < 2; ++i) {
        *(float4*)&dst[(r * 2 + i) * DDIM + c * 8]     = make_float4(acc[i][0], acc[i][1], acc[i][2], acc[i][3]);
        *(float4*)&dst[(r * 2 + i) * DDIM + c * 8 + 4] = make_float4(acc[i][4], acc[i][5], acc[i][6], acc[i][7]);
    }
}

// ---------------- decode kernel ----------------
__global__ void __launch_bounds__(NT, 3)
attn_decode_kernel(const float* __restrict__ x_in,
                   const float* __restrict__ k_in,
                   const float* __restrict__ v_in,
                   const float* __restrict__ wq,
                   const float* __restrict__ wk,
                   const float* __restrict__ wv,
                   const float* __restrict__ wo,
                   float* k_out, float* v_out, float* __restrict__ x_out)
{
    extern __shared__ float sm[];

    const int t = threadIdx.x;
    const int w = t >> 5;
    const int l = t & 31;
    const int h  = blockIdx.x >> 6;
    const int b0 = (blockIdx.x & 63) << 1;

    float* kg = k_out + (size_t)(b0 * HDIM + h) * (SDIM * DDIM);
    float* vg = v_out + (size_t)(b0 * HDIM + h) * (SDIM * DDIM);

    // ---- prologue: k_in -> k_out (global cache), v_in -> smem + v_out, x -> cur ----
    for (int b = 0; b < 2; ++b) {
        const float4* kin = (const float4*)(k_in + (size_t)((b0 + b) * HDIM + h) * (SDIM * DDIM));
        const float4* vin = (const float4*)(v_in + (size_t)((b0 + b) * HDIM + h) * (SDIM * DDIM));
        float4* kd = (float4*)(kg + (size_t)b * BSTR);
        float4* vd = (float4*)(vg + (size_t)b * BSTR);
        for (int i = t; i < SDIM * DDIM / 4; i += NT) {
            kd[i] = kin[i];
            float4 vv = vin[i];
            *(float4*)&sm[VS + b * 8192 + 4 * i] = vv;
            vd[i] = vv;
        }
        const float* xin = x_in + (size_t)((b0 + b) * HDIM + h) * DDIM;
        for (int d = t; d < DDIM; d += NT) sm[CUR + b * DDIM + d] = xin[d];
    }
    __syncthreads();

    // P1 flat split: 384 rows (q|k|v), warp w -> rows [48w, 48w+48)
    const int r0  = w * 48;
    const int mA  = r0 >> 7;
    const int dA  = r0 & 127;
    const int nA  = min(48, 128 - dA);
    const int nB  = 48 - nA;
    const int extra = (w > 2) + (w > 5);
    const int slotA = w + extra;
    const int slotB = slotA + 1;

    const float* origM[3] = { wq + (size_t)h * DDIM * DDIM,
                              wk + (size_t)h * DDIM * DDIM,
                              wv + (size_t)h * DDIM * DDIM };
    const float* Ch = g_comb + (size_t)h * 384 * DDIM;

    const float4* origA4  = (const float4*)(origM[mA] + (size_t)dA * DDIM);
    const float4* fusedA4 = (const float4*)(Ch + (size_t)r0 * DDIM);
    const float4* origB4  = (nB > 0) ? (const float4*)origM[mA + 1] : nullptr;
    const float4* fusedB4 = (const float4*)(Ch + (size_t)(r0 + nA) * DDIM);

    const int p2b = w >> 2, p2s0 = (w & 3) << 4;     // P2: (batch, s-quarter)
    const int p4b = t >> 7, p4d = t & 127;           // P4: (batch, d)

    for (int gen = STARTLEN; gen < SDIM; ++gen) {
        const bool first = (gen == STARTLEN);

        // ===== P1: balanced projections (48 rows/warp, 2 batches) =====
        {
            const float4* Wp = first ? origA4 : fusedA4;
            float4 a0 = {0,0,0,0}, a1 = {0,0,0,0};
            #pragma unroll 8
            for (int i = 0; i < nA; ++i) {
                float4 wv4 = Wp[i * 32 + l];
                float x0 = sm[CUR + dA + i];
                float x1 = sm[CUR + DDIM + dA + i];
                a0.x += x0 * wv4.x; a0.y += x0 * wv4.y; a0.z += x0 * wv4.z; a0.w += x0 * wv4.w;
                a1.x += x1 * wv4.x; a1.y += x1 * wv4.y; a1.z += x1 * wv4.z; a1.w += x1 * wv4.w;
            }
            *(float4*)&sm[RED + (slotA * 2 + 0) * DDIM + (l << 2)] = a0;
            *(float4*)&sm[RED + (slotA * 2 + 1) * DDIM + (l << 2)] = a1;
            if (nB > 0) {
                const float4* Wp2 = first ? origB4 : fusedB4;
                float4 c0 = {0,0,0,0}, c1 = {0,0,0,0};
                #pragma unroll 8
                for (int i = 0; i < nB; ++i) {
                    float4 wv4 = Wp2[i * 32 + l];
                    float x0 = sm[CUR + i];
                    float x1 = sm[CUR + DDIM + i];
                    c0.x += x0 * wv4.x; c0.y += x0 * wv4.y; c0.z += x0 * wv4.z; c0.w += x0 * wv4.w;
                    c1.x += x1 * wv4.x; c1.y += x1 * wv4.y; c1.z += x1 * wv4.z; c1.w += x1 * wv4.w;
                }
                *(float4*)&sm[RED + (slotB * 2 + 0) * DDIM + (l << 2)] = c0;
                *(float4*)&sm[RED + (slotB * 2 + 1) * DDIM + (l << 2)] = c1;
            }
        }
        __syncthreads();

        // ===== reduce: q -> RED rows 0-1 (scaled); k -> kg (global); v -> Vs + vg =====
        {
            const int b = t >> 7, e = t & 127;
            float qv = sm[RED + (0 + b) * DDIM + e] + sm[RED + (2 + b) * DDIM + e]
                     + sm[RED + (4 + b) * DDIM + e];
            float kv = sm[RED + (6 + b) * DDIM + e] + sm[RED + (8 + b) * DDIM + e]
                     + sm[RED + (10 + b) * DDIM + e] + sm[RED + (12 + b) * DDIM + e];
            float vv = sm[RED + (14 + b) * DDIM + e] + sm[RED + (16 + b) * DDIM + e]
                     + sm[RED + (18 + b) * DDIM + e];
            sm[RED + b * DDIM + e] = qv * 0.125f;
            kg[(size_t)b * BSTR + gen * DDIM + e] = kv;
            sm[VS + (b * SDIM + gen) * DDIM + e] = vv;
            vg[(size_t)b * BSTR + gen * DDIM + e] = vv;
        }
        __syncthreads();

        // ===== P2: QK scores from global K (high-MLP LDG.128) -> raw att =====
        {
            float4 q4 = *(const float4*)&sm[RED + p2b * DDIM + (l << 2)];
            const float4* kb4 = (const float4*)(kg + (size_t)p2b * BSTR) + l;
            #pragma unroll 8
            for (int r = 0; r < 16; ++r) {
                int s = p2s0 + r;
                float4 k4 = kb4[s * 32];
                float p = k4.x * q4.x + k4.y * q4.y + k4.z * q4.z + k4.w * q4.w;
                #pragma unroll
                for (int o = 16; o > 0; o >>= 1) p += __shfl_xor_sync(0xFFFFFFFFu, p, o);
                if (l == 0) sm[ATTB + p2b * SDIM + s] = p;
            }
        }
        __syncthreads();

        // ===== P4: per-warp register softmax + AV from smem V -> cur =====
        {
            float s0 = sm[ATTB + p4b * SDIM + l];
            float s1 = sm[ATTB + p4b * SDIM + 32 + l];
            float mx = fmaxf(s0, s1);
            #pragma unroll
            for (int o = 16; o > 0; o >>= 1) mx = fmaxf(mx, __shfl_xor_sync(0xFFFFFFFFu, mx, o));
            float e0 = __expf(s0 - mx);
            float e1 = __expf(s1 - mx);
            float su = e0 + e1;
            #pragma unroll
            for (int o = 16; o > 0; o >>= 1) su += __shfl_xor_sync(0xFFFFFFFFu, su, o);
            float inv = 1.0f / su;
            float p0 = e0 * inv, p1 = e1 * inv;

            const float* vb = sm + VS + p4b * (SDIM * DDIM) + p4d;
            float acc = 0.f;
            #pragma unroll 8
            for (int s = 0; s < 32; ++s) {
                float a = __shfl_sync(0xFFFFFFFFu, p0, s);
                acc += a * vb[s * DDIM];
            }
            #pragma unroll 8
            for (int s = 0; s < 32; ++s) {
                float a = __shfl_sync(0xFFFFFFFFu, p1, s);
                acc += a * vb[(32 + s) * DDIM];
            }
            sm[CUR + p4b * DDIM + p4d] = acc;
        }
        __syncthreads();
    }

    // ---- epilogue: x_out = cur @ Wo ----
    const float4* Wo4 = (const float4*)(wo + (size_t)h * DDIM * DDIM);
    {
        float4 a0 = {0,0,0,0}, a1 = {0,0,0,0};
        const int d0 = w << 4;
        #pragma unroll 8
        for (int dd = 0; dd < 16; ++dd) {
            int d = d0 + dd;
            float4 wv4 = Wo4[d * 32 + l];
            float x0 = sm[CUR + d];
            float x1 = sm[CUR + DDIM + d];
            a0.x += x0 * wv4.x; a0.y += x0 * wv4.y; a0.z += x0 * wv4.z; a0.w += x0 * wv4.w;
            a1.x += x1 * wv4.x; a1.y += x1 * wv4.y; a1.z += x1 * wv4.z; a1.w += x1 * wv4.w;
        }
        *(float4*)&sm[RED + ((w << 1) + 0) * DDIM + (l << 2)] = a0;
        *(float4*)&sm[RED + ((w << 1) + 1) * DDIM + (l << 2)] = a1;
    }
    __syncthreads();
    {
        const int b = t >> 7, e = t & 127;
        float v = 0.f;
        #pragma unroll
        for (int ww = 0; ww < 8; ++ww)
            v += sm[RED + ((ww << 1) + b) * DDIM + e];
        x_out[(size_t)((b0 + b) * HDIM + h) * DDIM + e] = v;
    }
}

extern "C" void kernel_launch(void* const* d_in, const int* in_sizes, int n_in,
                              void* d_out, int out_size)
{
    const float* x  = (const float*)d_in[0];
    const float* k  = (const float*)d_in[1];
    const float* v  = (const float*)d_in[2];
    const float* wq = (const float*)d_in[3];
    const float* wk = (const float*)d_in[4];
    const float* wv = (const float*)d_in[5];
    const float* wo = (const float*)d_in[6];

    float* out   = (float*)d_out;
    float* k_out = out;
    float* v_out = out + (size_t)BDIM * HDIM * SDIM * DDIM;
    float* x_out = out + (size_t)2 * BDIM * HDIM * SDIM * DDIM;

    fuse_weights_kernel<<<HDIM * 12, 256>>>(wq, wk, wv, wo);

    size_t smem = SMEM_FLOATS * sizeof(float);
    cudaFuncSetAttribute(attn_decode_kernel,
                         cudaFuncAttributeMaxDynamicSharedMemorySize, (int)smem);
    attn_decode_kernel<<<BDIM * HDIM / 2, NT, smem>>>(
        x, k, v, wq, wk, wv, wo, k_out, v_out, x_out);
}